// round 5
// baseline (speedup 1.0000x reference)
#include <cuda_runtime.h>
#include <cuda_bf16.h>
#include <math.h>
#include <stdint.h>

#define H 256
#define BM 64
#define MAXN 500000
#define MAXB 1024

// scratch (device globals: allocation-free rule)
__device__ float g_s[MAXN];
__device__ float g_w[MAXN];
__device__ int   g_seg[MAXB + 1];
__device__ int   g_is64;

// ---------------- helpers ----------------

__device__ __forceinline__ uint32_t bf2_pack(float a, float b) {
    __nv_bfloat162 h = __floats2bfloat162_rn(a, b);  // .x = a (low half)
    return *reinterpret_cast<uint32_t*>(&h);
}

__device__ __forceinline__ float bf_res(float a) {
    return a - __bfloat162float(__float2bfloat16_rn(a));  // exact in fp32
}

__device__ __forceinline__ void mma_bf16(float c[4], const uint32_t a[4],
                                         uint32_t b0, uint32_t b1) {
    asm volatile(
        "mma.sync.aligned.m16n8k16.row.col.f32.bf16.bf16.f32 "
        "{%0,%1,%2,%3}, {%4,%5,%6,%7}, {%8,%9}, {%0,%1,%2,%3};\n"
        : "+f"(c[0]), "+f"(c[1]), "+f"(c[2]), "+f"(c[3])
        : "r"(a[0]), "r"(a[1]), "r"(a[2]), "r"(a[3]), "r"(b0), "r"(b1));
}

__device__ __forceinline__ float tanh_fast(float z) {
    float e = __expf(2.0f * z);
    return 1.0f - 2.0f / (e + 1.0f);
}

// ---------------- kernel 0: detect batch dtype (int32 vs int64) ----------------
// For real int64 data, samples are in [0, B). For int32 data interpreted as
// int64, the high word holds a later (nonzero) batch id -> value >= 2^32.
__global__ void detect_kernel(const void* __restrict__ batch, int n, int B) {
    const long long* b64 = (const long long*)batch;
    int i0 = n / 2 - 1; if (i0 < 0) i0 = 0;
    int i1 = n / 4;     if (i1 >= n / 2) i1 = i0;
    long long v0 = b64[i0];   // byte range <= 4n: safe under either dtype
    long long v1 = b64[i1];
    g_is64 = (v0 >= 0 && v0 < B && v1 >= 0 && v1 < B) ? 1 : 0;
}

__device__ __forceinline__ int read_batch(const void* p, int i) {
    return g_is64 ? (int)((const long long*)p)[i] : ((const int*)p)[i];
}

// ---------------- kernel 1: segment boundaries ----------------
__global__ void seg_kernel(const void* __restrict__ batch, int n, int B) {
    int i = blockIdx.x * blockDim.x + threadIdx.x;
    if (i >= n) return;
    int b = read_batch(batch, i);
    b = b < 0 ? 0 : (b >= B ? B - 1 : b);
    if (i == 0) {
        for (int bb = 0; bb <= b; ++bb) g_seg[bb] = 0;
    } else {
        int pb = read_batch(batch, i - 1);
        pb = pb < 0 ? 0 : (pb >= B ? B - 1 : pb);
        if (pb != b)
            for (int bb = pb + 1; bb <= b; ++bb) g_seg[bb] = i;
    }
    if (i == n - 1) {
        for (int bb = b + 1; bb <= B; ++bb) g_seg[bb] = n;
    }
}

// ---------------- kernel 2: attention scores ----------------
// s[i] = tanh(x[i,:] @ W1 + b1) @ W2 + b2
// CTA: 64 nodes x 256 hidden; 8 warps = 2(M) x 4(N), warp tile 32x64.
// bf16 split-precision: Z = Xh*Wh + Xl*Wh + Xh*Wl (rel err ~2^-16).
// X streamed in 64x16 k-stages (stride 12: banks 12*gid+tig all distinct).
// W staged per 16-k slice (stride 264: banks 8*tig+gid all distinct).
// Static shared ~25.5 KB -> 2 CTAs/SM without attribute opt-in.
#define XS 12

__global__ void __launch_bounds__(256)
score_kernel(const float* __restrict__ x, const float* __restrict__ W1,
             const float* __restrict__ b1, const float* __restrict__ W2,
             const float* __restrict__ b2, int n) {
    __shared__ uint32_t XHs[BM * XS];
    __shared__ uint32_t XLs[BM * XS];
    __shared__ uint32_t WH[8 * 264];
    __shared__ uint32_t WL[8 * 264];
    __shared__ float b1s[H];
    __shared__ float w2s[H];
    __shared__ float ssh[BM * 4];

    const int tid   = threadIdx.x;
    const int lane  = tid & 31;
    const int warp  = tid >> 5;
    const int warpM = warp >> 2;   // 0..1
    const int warpN = warp & 3;    // 0..3
    const int gid   = lane >> 2;   // 0..7
    const int tig   = lane & 3;    // 0..3
    const long long m0 = (long long)blockIdx.x * BM;

    b1s[tid] = b1[tid];
    w2s[tid] = W2[tid];

    const int xr = tid >> 2;     // 0..63
    const int xc = tid & 3;      // 0..3
    const bool xok = (m0 + xr < n);
    const float* xrow = x + (m0 + xr) * (long long)H;

    // prefetch stage 0
    float wA[8], wB[8];
    #pragma unroll
    for (int j = 0; j < 8; ++j) {
        wA[j] = W1[(2 * j) * H + tid];
        wB[j] = W1[(2 * j + 1) * H + tid];
    }
    float4 xv = make_float4(0.f, 0.f, 0.f, 0.f);
    if (xok) xv = *(const float4*)(xrow + xc * 4);

    float acc[2][8][4];
    #pragma unroll
    for (int mt = 0; mt < 2; ++mt)
        #pragma unroll
        for (int nt = 0; nt < 8; ++nt)
            #pragma unroll
            for (int c = 0; c < 4; ++c) acc[mt][nt][c] = 0.0f;

    for (int kt = 0; kt < 16; ++kt) {
        __syncthreads();   // previous stage consumed
        #pragma unroll
        for (int j = 0; j < 8; ++j) {
            WH[j * 264 + tid] = bf2_pack(wA[j], wB[j]);
            WL[j * 264 + tid] = bf2_pack(bf_res(wA[j]), bf_res(wB[j]));
        }
        {
            int bidx = xr * XS + 2 * xc;
            XHs[bidx]     = bf2_pack(xv.x, xv.y);
            XHs[bidx + 1] = bf2_pack(xv.z, xv.w);
            XLs[bidx]     = bf2_pack(bf_res(xv.x), bf_res(xv.y));
            XLs[bidx + 1] = bf2_pack(bf_res(xv.z), bf_res(xv.w));
        }
        if (kt < 15) {
            #pragma unroll
            for (int j = 0; j < 8; ++j) {
                wA[j] = W1[((kt + 1) * 16 + 2 * j) * H + tid];
                wB[j] = W1[((kt + 1) * 16 + 2 * j + 1) * H + tid];
            }
            xv = make_float4(0.f, 0.f, 0.f, 0.f);
            if (xok) xv = *(const float4*)(xrow + (kt + 1) * 16 + xc * 4);
        }
        __syncthreads();

        uint32_t ah[2][4], al[2][4];
        #pragma unroll
        for (int mt = 0; mt < 2; ++mt) {
            int r0 = warpM * 32 + mt * 16 + gid;
            int i0 = r0 * XS + tig;
            int i1 = (r0 + 8) * XS + tig;
            ah[mt][0] = XHs[i0];     ah[mt][1] = XHs[i1];
            ah[mt][2] = XHs[i0 + 4]; ah[mt][3] = XHs[i1 + 4];
            al[mt][0] = XLs[i0];     al[mt][1] = XLs[i1];
            al[mt][2] = XLs[i0 + 4]; al[mt][3] = XLs[i1 + 4];
        }
        #pragma unroll
        for (int nt = 0; nt < 8; ++nt) {
            int cB = warpN * 64 + nt * 8 + gid;
            uint32_t bh0 = WH[tig * 264 + cB];
            uint32_t bh1 = WH[(tig + 4) * 264 + cB];
            uint32_t bl0 = WL[tig * 264 + cB];
            uint32_t bl1 = WL[(tig + 4) * 264 + cB];
            mma_bf16(acc[0][nt], ah[0], bh0, bh1);
            mma_bf16(acc[1][nt], ah[1], bh0, bh1);
            mma_bf16(acc[0][nt], al[0], bh0, bh1);
            mma_bf16(acc[1][nt], al[1], bh0, bh1);
            mma_bf16(acc[0][nt], ah[0], bl0, bl1);
            mma_bf16(acc[1][nt], ah[1], bl0, bl1);
        }
    }

    // epilogue: s_row = sum_cols tanh(z + b1) * w2 (no atomics)
    #pragma unroll
    for (int mt = 0; mt < 2; ++mt) {
        float p0 = 0.0f, p1 = 0.0f;
        #pragma unroll
        for (int nt = 0; nt < 8; ++nt) {
            int c0 = warpN * 64 + nt * 8 + 2 * tig;
            float w0 = w2s[c0], w1v = w2s[c0 + 1];
            float e0 = b1s[c0], e1 = b1s[c0 + 1];
            p0 += w0 * tanh_fast(acc[mt][nt][0] + e0) + w1v * tanh_fast(acc[mt][nt][1] + e1);
            p1 += w0 * tanh_fast(acc[mt][nt][2] + e0) + w1v * tanh_fast(acc[mt][nt][3] + e1);
        }
        p0 += __shfl_xor_sync(0xffffffffu, p0, 1);
        p0 += __shfl_xor_sync(0xffffffffu, p0, 2);
        p1 += __shfl_xor_sync(0xffffffffu, p1, 1);
        p1 += __shfl_xor_sync(0xffffffffu, p1, 2);
        if (tig == 0) {
            int row0 = warpM * 32 + mt * 16 + gid;
            ssh[row0 * 4 + warpN]       = p0;
            ssh[(row0 + 8) * 4 + warpN] = p1;
        }
    }
    __syncthreads();
    if (tid < BM && m0 + tid < n) {
        float s = ssh[tid * 4] + ssh[tid * 4 + 1] + ssh[tid * 4 + 2] + ssh[tid * 4 + 3];
        g_s[m0 + tid] = s + b2[0];
    }
}

// ---------------- kernel 3: segment softmax -> weights ----------------
__device__ __forceinline__ float block_reduce(float v, bool do_max) {
    __shared__ float red[8];
    __shared__ float res;
    #pragma unroll
    for (int o = 16; o; o >>= 1) {
        float t = __shfl_xor_sync(0xffffffffu, v, o);
        v = do_max ? fmaxf(v, t) : (v + t);
    }
    if ((threadIdx.x & 31) == 0) red[threadIdx.x >> 5] = v;
    __syncthreads();
    if (threadIdx.x == 0) {
        float r = red[0];
        for (int i = 1; i < 8; ++i) r = do_max ? fmaxf(r, red[i]) : (r + red[i]);
        res = r;
    }
    __syncthreads();
    float out = res;
    __syncthreads();
    return out;
}

__global__ void stats_kernel() {
    int b = blockIdx.x;
    int start = g_seg[b], end = g_seg[b + 1];
    if (start >= end) return;
    float m = -INFINITY;
    for (int i = start + threadIdx.x; i < end; i += 256) m = fmaxf(m, g_s[i]);
    m = block_reduce(m, true);
    float dsum = 0.0f;
    for (int i = start + threadIdx.x; i < end; i += 256) dsum += __expf(g_s[i] - m);
    float d = block_reduce(dsum, false);
    float inv = 1.0f / d;
    for (int i = start + threadIdx.x; i < end; i += 256) g_w[i] = __expf(g_s[i] - m) * inv;
}

// ---------------- kernel 4: fused mean/max/attn pooling ----------------
__global__ void pool_kernel(const float* __restrict__ x, float* __restrict__ out, int B) {
    int b = blockIdx.x;
    int start = g_seg[b], end = g_seg[b + 1];
    int len = end - start;
    float* orow = out + (long long)b * (3 * H);

    if (len <= 0) {
        for (int j = threadIdx.x; j < 3 * H; j += 256) orow[j] = 0.0f;
        return;
    }

    int r = threadIdx.x >> 6;   // 0..3
    int c = threadIdx.x & 63;   // 0..63 (float4 col)

    float4 sum = make_float4(0.f, 0.f, 0.f, 0.f);
    float4 att = make_float4(0.f, 0.f, 0.f, 0.f);
    float4 mx  = make_float4(-INFINITY, -INFINITY, -INFINITY, -INFINITY);

    for (int i = start + r; i < end; i += 4) {
        float wi = g_w[i];
        float4 xv = *(const float4*)(x + (long long)i * H + c * 4);
        sum.x += xv.x; sum.y += xv.y; sum.z += xv.z; sum.w += xv.w;
        mx.x = fmaxf(mx.x, xv.x); mx.y = fmaxf(mx.y, xv.y);
        mx.z = fmaxf(mx.z, xv.z); mx.w = fmaxf(mx.w, xv.w);
        att.x += wi * xv.x; att.y += wi * xv.y;
        att.z += wi * xv.z; att.w += wi * xv.w;
    }

    __shared__ float4 shsum[4][64];
    __shared__ float4 shmax[4][64];
    __shared__ float4 shatt[4][64];
    shsum[r][c] = sum; shmax[r][c] = mx; shatt[r][c] = att;
    __syncthreads();

    if (r == 0) {
        #pragma unroll
        for (int rr = 1; rr < 4; ++rr) {
            float4 s2 = shsum[rr][c], m2 = shmax[rr][c], a2 = shatt[rr][c];
            sum.x += s2.x; sum.y += s2.y; sum.z += s2.z; sum.w += s2.w;
            mx.x = fmaxf(mx.x, m2.x); mx.y = fmaxf(mx.y, m2.y);
            mx.z = fmaxf(mx.z, m2.z); mx.w = fmaxf(mx.w, m2.w);
            att.x += a2.x; att.y += a2.y; att.z += a2.z; att.w += a2.w;
        }
        float inv = 1.0f / (float)len;
        float4 mean = make_float4(sum.x * inv, sum.y * inv, sum.z * inv, sum.w * inv);
        *(float4*)(orow + c * 4)         = mean;
        *(float4*)(orow + H + c * 4)     = mx;
        *(float4*)(orow + 2 * H + c * 4) = att;
    }
}

// ---------------- launch ----------------
extern "C" void kernel_launch(void* const* d_in, const int* in_sizes, int n_in,
                              void* d_out, int out_size) {
    const float* x     = (const float*)d_in[0];
    const void*  batch = d_in[1];
    const float* W1    = (const float*)d_in[2];
    const float* b1    = (const float*)d_in[3];
    const float* W2    = (const float*)d_in[4];
    const float* b2    = (const float*)d_in[5];
    float*       out   = (float*)d_out;

    int n = in_sizes[1];
    int B = out_size / (3 * H);

    detect_kernel<<<1, 1>>>(batch, n, B);
    seg_kernel<<<(n + 255) / 256, 256>>>(batch, n, B);
    score_kernel<<<(n + BM - 1) / BM, 256>>>(x, W1, b1, W2, b2, n);
    stats_kernel<<<B, 256>>>();
    pool_kernel<<<B, 256>>>(x, out, B);
}